// round 10
// baseline (speedup 1.0000x reference)
#include <cuda_runtime.h>
#include <cuda_bf16.h>
#include <cstdint>

#define NN 200000
#define PADK 200704      // 98*2048, padded row count (>= 1563*128 too)
#define NA 300
#define NAP 320
#define NF 128
#define NC 32

#define SLICE_K 2048
#define NSLICE 98        // 98*2048 = 200704 == PADK
#define KT 32            // k-tile for both passes

// ---------------- device scratch (row-padded to PADK) ----------------
__device__ __nv_bfloat16 g_adj_hi[(size_t)PADK * NAP];
__device__ __nv_bfloat16 g_adj_lo[(size_t)PADK * NAP];
__device__ __nv_bfloat16 g_hh[(size_t)PADK * NF];
__device__ __nv_bfloat16 g_hl[(size_t)PADK * NF];
__device__ float g_U[384 * NF];
__device__ __nv_bfloat16 g_MT_hi[NF * NAP];
__device__ __nv_bfloat16 g_MT_lo[NF * NAP];
__device__ float g_rowsum[NN];
__device__ float g_colsum[384];

// ---------------- helpers ----------------
__device__ __forceinline__ uint32_t smem_u32(const void* p) {
    uint32_t a;
    asm("{ .reg .u64 t; cvta.to.shared.u64 t, %1; cvt.u32.u64 %0, t; }"
        : "=r"(a) : "l"(p));
    return a;
}
__device__ __forceinline__ void cpa(uint32_t dst, const void* src) {
    asm volatile("cp.async.cg.shared.global [%0], [%1], 16;"
                 :: "r"(dst), "l"(src) : "memory");
}
__device__ __forceinline__ void cpa_commit() {
    asm volatile("cp.async.commit_group;" ::: "memory");
}
template<int N> __device__ __forceinline__ void cpa_wait() {
    asm volatile("cp.async.wait_group %0;" :: "n"(N) : "memory");
}
__device__ __forceinline__ void ldm4(uint32_t* r, uint32_t a) {
    asm volatile("ldmatrix.sync.aligned.m8n8.x4.shared.b16 {%0,%1,%2,%3}, [%4];"
        : "=r"(r[0]), "=r"(r[1]), "=r"(r[2]), "=r"(r[3]) : "r"(a));
}
__device__ __forceinline__ void ldm4t(uint32_t* r, uint32_t a) {
    asm volatile("ldmatrix.sync.aligned.m8n8.x4.trans.shared.b16 {%0,%1,%2,%3}, [%4];"
        : "=r"(r[0]), "=r"(r[1]), "=r"(r[2]), "=r"(r[3]) : "r"(a));
}
__device__ __forceinline__ void mma16816(float* d, const uint32_t* a, const uint32_t* b) {
    asm volatile("mma.sync.aligned.m16n8k16.row.col.f32.bf16.bf16.f32 "
        "{%0,%1,%2,%3}, {%4,%5,%6,%7}, {%8,%9}, {%0,%1,%2,%3};"
        : "+f"(d[0]), "+f"(d[1]), "+f"(d[2]), "+f"(d[3])
        : "r"(a[0]), "r"(a[1]), "r"(a[2]), "r"(a[3]), "r"(b[0]), "r"(b[1]));
}

__device__ __forceinline__ void split1(float v, __nv_bfloat16& h, __nv_bfloat16& l) {
    h = __float2bfloat16(v);
    l = __float2bfloat16(v - __bfloat162float(h));
}
__device__ __forceinline__ void split2(float v0, float v1, uint32_t& hi, uint32_t& lo) {
    __nv_bfloat16 h0, l0, h1, l1;
    split1(v0, h0, l0); split1(v1, h1, l1);
    __nv_bfloat162 hp = __halves2bfloat162(h0, h1);
    __nv_bfloat162 lp = __halves2bfloat162(l0, l1);
    hi = *reinterpret_cast<uint32_t*>(&hp);
    lo = *reinterpret_cast<uint32_t*>(&lp);
}

// ---------------------------------------------------------------------------
__global__ void init_kernel() {
    int i = blockIdx.x * blockDim.x + threadIdx.x;
    if (i < 384 * NF) g_U[i] = 0.f;
    if (i < 384) g_colsum[i] = 0.f;
    if (i < NF * NAP / 2) {
        reinterpret_cast<uint32_t*>(g_MT_hi)[i] = 0u;
        reinterpret_cast<uint32_t*>(g_MT_lo)[i] = 0u;
    }
}

// zero the padded rows [NN, PADK) of adj and h arrays (so hot loops need no bounds)
#define PADR (PADK - NN)   // 704
__global__ void pad_kernel() {
    int i = blockIdx.x * blockDim.x + threadIdx.x;
    int aw = PADR * NAP / 2;   // u32 words per adj array pad
    int hw = PADR * NF / 2;    // u32 words per h array pad
    if (i < aw) {
        reinterpret_cast<uint32_t*>(g_adj_hi + (size_t)NN * NAP)[i] = 0u;
        reinterpret_cast<uint32_t*>(g_adj_lo + (size_t)NN * NAP)[i] = 0u;
    }
    if (i < hw) {
        reinterpret_cast<uint32_t*>(g_hh + (size_t)NN * NF)[i] = 0u;
        reinterpret_cast<uint32_t*>(g_hl + (size_t)NN * NF)[i] = 0u;
    }
}

// ---------------------------------------------------------------------------
// adj -> bf16 hi/lo (padded 320 cols) + rowsum + colsum in one pass
// ---------------------------------------------------------------------------
__device__ __forceinline__ void w4(__nv_bfloat16* ph, __nv_bfloat16* pl, float4 v) {
    uint32_t hA, lA, hB, lB;
    split2(v.x, v.y, hA, lA);
    split2(v.z, v.w, hB, lB);
    *reinterpret_cast<uint2*>(ph) = make_uint2(hA, hB);
    *reinterpret_cast<uint2*>(pl) = make_uint2(lA, lB);
}

#define CONV_ROWS 250
__global__ void __launch_bounds__(256) conv_adj_kernel(const float* __restrict__ adj) {
    const int tx = threadIdx.x & 31;
    const int ty = threadIdx.x >> 5;
    const int r0 = blockIdx.x * CONV_ROWS;
    const int r1 = min(r0 + CONV_ROWS, NN);

    float ca[12];
#pragma unroll
    for (int j = 0; j < 12; j++) ca[j] = 0.f;

    for (int r = r0 + ty; r < r1; r += 8) {
        const float4* row4 = (const float4*)(adj + (size_t)r * NA);
        float4 v0 = row4[tx];
        float4 v1 = row4[32 + tx];
        float4 v2 = (tx < 11) ? row4[64 + tx] : make_float4(0.f, 0.f, 0.f, 0.f);
        ca[0] += v0.x; ca[1] += v0.y; ca[2]  += v0.z; ca[3]  += v0.w;
        ca[4] += v1.x; ca[5] += v1.y; ca[6]  += v1.z; ca[7]  += v1.w;
        ca[8] += v2.x; ca[9] += v2.y; ca[10] += v2.z; ca[11] += v2.w;
        float rp = v0.x + v0.y + v0.z + v0.w
                 + v1.x + v1.y + v1.z + v1.w
                 + v2.x + v2.y + v2.z + v2.w;
#pragma unroll
        for (int o = 16; o > 0; o >>= 1)
            rp += __shfl_down_sync(0xffffffffu, rp, o);
        if (tx == 0) g_rowsum[r] = rp;

        __nv_bfloat16* oh = g_adj_hi + (size_t)r * NAP;
        __nv_bfloat16* ol = g_adj_lo + (size_t)r * NAP;
        w4(oh + 4 * tx,        ol + 4 * tx,        v0);
        w4(oh + 4 * (32 + tx), ol + 4 * (32 + tx), v1);
        if (tx < 16) w4(oh + 4 * (64 + tx), ol + 4 * (64 + tx), v2);
    }

    __shared__ float sc[8][12][32];
#pragma unroll
    for (int j = 0; j < 12; j++) sc[ty][j][tx] = ca[j];
    __syncthreads();
    if (ty == 0) {
#pragma unroll
        for (int j = 0; j < 12; j++) {
            float s = 0.f;
#pragma unroll
            for (int t = 0; t < 8; t++) s += sc[t][j][tx];
            int col = (j >> 2) * 128 + tx * 4 + (j & 3);
            if (col < NA) atomicAdd(&g_colsum[col], s);
        }
    }
}

// ---------------------------------------------------------------------------
__global__ void conv_x_kernel(const float* __restrict__ x) {
    size_t i = (size_t)blockIdx.x * blockDim.x + threadIdx.x;
    if (i < (size_t)NN * NF / 4) {
        float4 v = ((const float4*)x)[i];
        uint32_t hA, lA, hB, lB;
        split2(v.x, v.y, hA, lA);
        split2(v.z, v.w, hB, lB);
        *reinterpret_cast<uint2*>(g_hh + 4 * i) = make_uint2(hA, hB);
        *reinterpret_cast<uint2*>(g_hl + 4 * i) = make_uint2(lA, lB);
    }
}

// ---------------------------------------------------------------------------
// upass: U[a][d] += sum_k adj[k][a]*h[k][d].  grid(5 a-tiles of 64, 98 slices).
// 128 thr, 4 warps (2m x 2n), warp tile 32a x 64d. KT=32, double-buffered.
// Bounds-free affine loads (rows padded to PADK); t-loop unrolled x2.
// ---------------------------------------------------------------------------
#define U_PA 144
#define U_PB 272
#define U_SA (KT * U_PA)       // 4608
#define U_SB (KT * U_PB)       // 8704
#define U_STAGE (2 * U_SA + 2 * U_SB)   // 26624

__device__ __forceinline__ void upass_load(uint32_t base, size_t kt, int a0, int tid) {
#pragma unroll
    for (int it = 0; it < 4; it++) {               // A: 2 bufs x 256 chunks
        int idx = tid + it * 128;
        int buf = idx >> 8, rem = idx & 255;
        int row = rem >> 3, c = rem & 7;
        const __nv_bfloat16* src = (buf ? g_adj_lo : g_adj_hi)
                                   + (kt + row) * NAP + a0 + c * 8;
        cpa(base + buf * U_SA + row * U_PA + c * 16, src);
    }
#pragma unroll
    for (int it = 0; it < 8; it++) {               // B: 2 bufs x 512 chunks
        int idx = tid + it * 128;
        int buf = idx >> 9, rem = idx & 511;
        int row = rem >> 4, c = rem & 15;
        const __nv_bfloat16* src = (buf ? g_hl : g_hh) + (kt + row) * NF + c * 8;
        cpa(base + 2 * U_SA + buf * U_SB + row * U_PB + c * 16, src);
    }
}

__global__ void __launch_bounds__(128) upass_kernel() {
    extern __shared__ char smem[];
    const uint32_t sb = smem_u32(smem);
    const int tid = threadIdx.x;
    const int wid = tid >> 5, L = tid & 31;
    const int a0 = blockIdx.x * 64;
    const size_t k0 = (size_t)blockIdx.y * SLICE_K;
    const int warp_m = wid >> 1, warp_n = wid & 1;

    float acc[2][8][4];
#pragma unroll
    for (int i = 0; i < 2; i++)
#pragma unroll
        for (int j = 0; j < 8; j++)
#pragma unroll
            for (int q = 0; q < 4; q++) acc[i][j][q] = 0.f;

    upass_load(sb, k0, a0, tid);   // stage 0
    cpa_commit();

    const int T = SLICE_K / KT;  // 64
#pragma unroll 2
    for (int t = 0; t < T; t++) {
        cpa_wait<0>();
        __syncthreads();
        if (t + 1 < T) {
            upass_load(sb + ((t + 1) & 1) * U_STAGE, k0 + (size_t)(t + 1) * KT, a0, tid);
            cpa_commit();
        }
        const uint32_t st = sb + (t & 1) * U_STAGE;
        const uint32_t Ah = st, Al = st + U_SA;
        const uint32_t Bh = st + 2 * U_SA, Bl = Bh + U_SB;

#pragma unroll
        for (int ks = 0; ks < 2; ks++) {
            // A (trans): row = ks*16 + ((L>>4)&1)*8 + (L&7); col += ((L>>3)&1)*8
            const uint32_t aoff = (uint32_t)(ks * 16 + ((L >> 4) & 1) * 8 + (L & 7)) * U_PA
                                + ((L >> 3) & 1) * 16;
            uint32_t AF[2][2][4];
#pragma unroll
            for (int mb = 0; mb < 2; mb++) {
                uint32_t c2 = (uint32_t)(warp_m * 32 + mb * 16) * 2;
                ldm4t(AF[0][mb], Ah + aoff + c2);
                ldm4t(AF[1][mb], Al + aoff + c2);
            }
            // B (trans): row = ks*16 + ((L>>3)&1)*8 + (L&7); col += ((L>>4)&1)*8
            const uint32_t boff = (uint32_t)(ks * 16 + ((L >> 3) & 1) * 8 + (L & 7)) * U_PB
                                + ((L >> 4) & 1) * 16;
            uint32_t BF[2][4][4];
#pragma unroll
            for (int nb = 0; nb < 4; nb++) {
                uint32_t c2 = (uint32_t)(warp_n * 64 + nb * 16) * 2;
                ldm4t(BF[0][nb], Bh + boff + c2);
                ldm4t(BF[1][nb], Bl + boff + c2);
            }
#pragma unroll
            for (int mb = 0; mb < 2; mb++)
#pragma unroll
                for (int j = 0; j < 8; j++) {
                    const uint32_t* bh = &BF[0][j >> 1][(j & 1) * 2];
                    const uint32_t* bl = &BF[1][j >> 1][(j & 1) * 2];
                    mma16816(acc[mb][j], AF[0][mb], bh);
                    mma16816(acc[mb][j], AF[0][mb], bl);
                    mma16816(acc[mb][j], AF[1][mb], bh);
                }
        }
    }

#pragma unroll
    for (int mb = 0; mb < 2; mb++) {
        int a = a0 + warp_m * 32 + mb * 16 + (L >> 2);
#pragma unroll
        for (int j = 0; j < 8; j++) {
            int d = warp_n * 64 + j * 8 + (L & 3) * 2;
            atomicAdd(&g_U[a * NF + d],           acc[mb][j][0]);
            atomicAdd(&g_U[a * NF + d + 1],       acc[mb][j][1]);
            atomicAdd(&g_U[(a + 8) * NF + d],     acc[mb][j][2]);
            atomicAdd(&g_U[(a + 8) * NF + d + 1], acc[mb][j][3]);
        }
    }
}

// ---------------------------------------------------------------------------
// mkM: M^T[d][a] = (U[a] @ W)[d] / clamp(colsum[a]) as bf16 hi/lo; zero U row.
// ---------------------------------------------------------------------------
template<int DOUT>
__global__ void mkM_kernel(const float* __restrict__ W) {
    __shared__ float u_s[NF];
    const int a = blockIdx.x;
    const int d = threadIdx.x;
    u_s[d] = g_U[a * NF + d];
    __syncthreads();
    g_U[a * NF + d] = 0.f;
    if (d < DOUT) {
        float cinv = 1.f / fmaxf(g_colsum[a], 1e-12f);
        float acc = 0.f;
#pragma unroll 8
        for (int k = 0; k < NF; k++)
            acc += u_s[k] * W[k * DOUT + d];
        __nv_bfloat16 hb, lb;
        split1(acc * cinv, hb, lb);
        g_MT_hi[d * NAP + a] = hb;
        g_MT_lo[d * NAP + a] = lb;
    }
}

// ---------------------------------------------------------------------------
// ppass: C[n][d] = sum_a adj[n][a]*M[a][d]; epilogue scales by 1/rowsum,
// relu+re-split (hidden) or fp32 write (final). 512 thr, 16 warps.
// Bounds-free affine A loads (rows padded); t-loop unrolled x2.
// ---------------------------------------------------------------------------
template<int NOUT, bool FINAL>
__global__ void __launch_bounds__(512) ppass_kernel(float* __restrict__ out) {
    constexpr int WM = (NOUT == 128) ? 4 : 8;
    constexpr int WN = 16 / WM;
    constexpr int MT = 128 / WM;
    constexpr int NT = NOUT / WN;
    constexpr int MB = MT / 16;
    constexpr int N8 = NT / 8;
    constexpr int NBP = NT / 16;
    constexpr int P = 80;
    constexpr int SA = 128 * P;
    constexpr int SB = NOUT * P;
    constexpr int STG = 2 * SA + 2 * SB;
    constexpr int BCH = NOUT * 8;

    extern __shared__ char smem[];
    const uint32_t sb = smem_u32(smem);
    const int tid = threadIdx.x, wid = tid >> 5, L = tid & 31;
    const int warp_m = wid / WN, warp_n = wid % WN;
    const size_t n0 = (size_t)blockIdx.x * 128;

    float acc[MB][N8][4];
#pragma unroll
    for (int i = 0; i < MB; i++)
#pragma unroll
        for (int j = 0; j < N8; j++)
#pragma unroll
            for (int q = 0; q < 4; q++) acc[i][j][q] = 0.f;

    auto load_tile = [&](int t, int stage) {
        uint32_t base = sb + stage * STG;
#pragma unroll
        for (int it = 0; it < 2; it++) {           // A: bounds-free (padded rows)
            int idx = tid + it * 512;
            int buf = idx >> 9, rem = idx & 511;
            int row = rem >> 2, c = rem & 3;
            const __nv_bfloat16* src = (buf ? g_adj_lo : g_adj_hi)
                                       + (n0 + row) * NAP + t * KT + c * 8;
            cpa(base + buf * SA + row * P + c * 16, src);
        }
        if (tid < BCH) {
            int buf = tid / (BCH / 2), rem = tid % (BCH / 2);
            int row = rem >> 2, c = rem & 3;
            const __nv_bfloat16* src = (buf ? g_MT_lo : g_MT_hi) + row * NAP + t * KT + c * 8;
            cpa(base + 2 * SA + buf * SB + row * P + c * 16, src);
        }
        if (BCH > 512 && tid + 512 < BCH) {
            int idx = tid + 512;
            int buf = idx / (BCH / 2), rem = idx % (BCH / 2);
            int row = rem >> 2, c = rem & 3;
            const __nv_bfloat16* src = (buf ? g_MT_lo : g_MT_hi) + row * NAP + t * KT + c * 8;
            cpa(base + 2 * SA + buf * SB + row * P + c * 16, src);
        }
    };

    load_tile(0, 0);
    cpa_commit();

    const int T = NAP / KT;  // 10
#pragma unroll 2
    for (int t = 0; t < T; t++) {
        cpa_wait<0>();
        __syncthreads();
        if (t + 1 < T) {
            load_tile(t + 1, (t + 1) & 1);
            cpa_commit();
        }
        const uint32_t st = sb + (t & 1) * STG;
        const uint32_t Ah = st, Al = st + SA;
        const uint32_t Bh = st + 2 * SA, Bl = Bh + SB;

#pragma unroll
        for (int ks = 0; ks < 2; ks++) {
            const uint32_t aoff = (uint32_t)(((L >> 3) & 1) * 8 + (L & 7)) * P
                                + ks * 32 + ((L >> 4) & 1) * 16;
            uint32_t AF[2][MB][4];
#pragma unroll
            for (int mb = 0; mb < MB; mb++) {
                uint32_t ro = (uint32_t)(warp_m * MT + mb * 16) * P;
                ldm4(AF[0][mb], Ah + ro + aoff);
                ldm4(AF[1][mb], Al + ro + aoff);
            }
            const uint32_t boff = (uint32_t)(((L >> 4) & 1) * 8 + (L & 7)) * P
                                + ks * 32 + ((L >> 3) & 1) * 16;
            uint32_t BF[2][NBP][4];
#pragma unroll
            for (int nb = 0; nb < NBP; nb++) {
                uint32_t ro = (uint32_t)(warp_n * NT + nb * 16) * P;
                ldm4(BF[0][nb], Bh + ro + boff);
                ldm4(BF[1][nb], Bl + ro + boff);
            }
#pragma unroll
            for (int mb = 0; mb < MB; mb++)
#pragma unroll
                for (int j = 0; j < N8; j++) {
                    const uint32_t* bh = &BF[0][j >> 1][(j & 1) * 2];
                    const uint32_t* bl = &BF[1][j >> 1][(j & 1) * 2];
                    mma16816(acc[mb][j], AF[0][mb], bh);
                    mma16816(acc[mb][j], AF[0][mb], bl);
                    mma16816(acc[mb][j], AF[1][mb], bh);
                }
        }
    }

    // epilogue (bounds kept here; outside hot loop)
#pragma unroll
    for (int mb = 0; mb < MB; mb++) {
        size_t r0 = n0 + warp_m * MT + mb * 16 + (L >> 2);
        size_t r1 = r0 + 8;
        float ri0 = (r0 < NN) ? 1.f / fmaxf(g_rowsum[r0], 1e-12f) : 0.f;
        float ri1 = (r1 < NN) ? 1.f / fmaxf(g_rowsum[r1], 1e-12f) : 0.f;
#pragma unroll
        for (int j = 0; j < N8; j++) {
            int d = warp_n * NT + j * 8 + (L & 3) * 2;
            if (FINAL) {
                if (r0 < NN) {
                    float2 o = make_float2(acc[mb][j][0] * ri0, acc[mb][j][1] * ri0);
                    *(float2*)(out + r0 * NC + d) = o;
                }
                if (r1 < NN) {
                    float2 o = make_float2(acc[mb][j][2] * ri1, acc[mb][j][3] * ri1);
                    *(float2*)(out + r1 * NC + d) = o;
                }
            } else {
                if (r0 < NN) {
                    float v0 = fmaxf(acc[mb][j][0] * ri0, 0.f);
                    float v1 = fmaxf(acc[mb][j][1] * ri0, 0.f);
                    uint32_t hi, lo;
                    split2(v0, v1, hi, lo);
                    *(uint32_t*)(g_hh + r0 * NF + d) = hi;
                    *(uint32_t*)(g_hl + r0 * NF + d) = lo;
                }
                if (r1 < NN) {
                    float v0 = fmaxf(acc[mb][j][2] * ri1, 0.f);
                    float v1 = fmaxf(acc[mb][j][3] * ri1, 0.f);
                    uint32_t hi, lo;
                    split2(v0, v1, hi, lo);
                    *(uint32_t*)(g_hh + r1 * NF + d) = hi;
                    *(uint32_t*)(g_hl + r1 * NF + d) = lo;
                }
            }
        }
    }
}

// ---------------------------------------------------------------------------
extern "C" void kernel_launch(void* const* d_in, const int* in_sizes, int n_in,
                              void* d_out, int out_size) {
    const float* x   = (const float*)d_in[0];
    const float* adj = (const float*)d_in[1];
    const float* W1  = (const float*)d_in[2];
    const float* W2  = (const float*)d_in[3];
    const float* W3  = (const float*)d_in[4];
    float* out = (float*)d_out;

    cudaFuncSetAttribute(upass_kernel,
                         cudaFuncAttributeMaxDynamicSharedMemorySize, 2 * U_STAGE);
    cudaFuncSetAttribute(ppass_kernel<128, false>,
                         cudaFuncAttributeMaxDynamicSharedMemorySize, 81920);
    cudaFuncSetAttribute(ppass_kernel<32, true>,
                         cudaFuncAttributeMaxDynamicSharedMemorySize, 51200);

    init_kernel<<<192, 256>>>();
    pad_kernel<<<(PADR * NAP / 2 + 255) / 256, 256>>>();
    conv_adj_kernel<<<800, 256>>>(adj);
    conv_x_kernel<<<25600, 256>>>(x);

    dim3 ugrid(5, NSLICE);

    upass_kernel<<<ugrid, 128, 2 * U_STAGE>>>();
    mkM_kernel<128><<<NA, 128>>>(W1);
    ppass_kernel<128, false><<<1563, 512, 81920>>>(nullptr);

    upass_kernel<<<ugrid, 128, 2 * U_STAGE>>>();
    mkM_kernel<128><<<NA, 128>>>(W2);
    ppass_kernel<128, false><<<1563, 512, 81920>>>(nullptr);

    upass_kernel<<<ugrid, 128, 2 * U_STAGE>>>();
    mkM_kernel<32><<<NA, 128>>>(W3);
    ppass_kernel<32, true><<<1563, 512, 51200>>>(out);
}

// round 11
// speedup vs baseline: 1.0543x; 1.0543x over previous
#include <cuda_runtime.h>
#include <cuda_bf16.h>
#include <cstdint>

#define NN 200000
#define PADK 200704      // 98*2048 padded rows (>= 1563*128)
#define NA 300
#define NAP 320
#define NF 128
#define NC 32

#define SLICE_K 2048
#define NSLICE 98
#define KT 32

// ---------------- device scratch (row-padded to PADK) ----------------
__device__ __nv_bfloat16 g_adj_hi[(size_t)PADK * NAP];
__device__ __nv_bfloat16 g_adj_lo[(size_t)PADK * NAP];
__device__ __nv_bfloat16 g_hh[(size_t)PADK * NF];
__device__ __nv_bfloat16 g_hl[(size_t)PADK * NF];
__device__ float g_U[384 * NF];
__device__ __nv_bfloat16 g_MT_hi[NF * NAP];
__device__ __nv_bfloat16 g_MT_lo[NF * NAP];
__device__ float g_rowsum[NN];
__device__ float g_colsum[384];

// ---------------- helpers ----------------
__device__ __forceinline__ uint32_t smem_u32(const void* p) {
    uint32_t a;
    asm("{ .reg .u64 t; cvta.to.shared.u64 t, %1; cvt.u32.u64 %0, t; }"
        : "=r"(a) : "l"(p));
    return a;
}
__device__ __forceinline__ void cpa(uint32_t dst, const void* src) {
    asm volatile("cp.async.cg.shared.global [%0], [%1], 16;"
                 :: "r"(dst), "l"(src) : "memory");
}
__device__ __forceinline__ void cpa_commit() {
    asm volatile("cp.async.commit_group;" ::: "memory");
}
template<int N> __device__ __forceinline__ void cpa_wait() {
    asm volatile("cp.async.wait_group %0;" :: "n"(N) : "memory");
}
__device__ __forceinline__ void ldm4(uint32_t* r, uint32_t a) {
    asm volatile("ldmatrix.sync.aligned.m8n8.x4.shared.b16 {%0,%1,%2,%3}, [%4];"
        : "=r"(r[0]), "=r"(r[1]), "=r"(r[2]), "=r"(r[3]) : "r"(a));
}
__device__ __forceinline__ void ldm4t(uint32_t* r, uint32_t a) {
    asm volatile("ldmatrix.sync.aligned.m8n8.x4.trans.shared.b16 {%0,%1,%2,%3}, [%4];"
        : "=r"(r[0]), "=r"(r[1]), "=r"(r[2]), "=r"(r[3]) : "r"(a));
}
__device__ __forceinline__ void mma16816(float* d, const uint32_t* a, const uint32_t* b) {
    asm volatile("mma.sync.aligned.m16n8k16.row.col.f32.bf16.bf16.f32 "
        "{%0,%1,%2,%3}, {%4,%5,%6,%7}, {%8,%9}, {%0,%1,%2,%3};"
        : "+f"(d[0]), "+f"(d[1]), "+f"(d[2]), "+f"(d[3])
        : "r"(a[0]), "r"(a[1]), "r"(a[2]), "r"(a[3]), "r"(b[0]), "r"(b[1]));
}

__device__ __forceinline__ void split1(float v, __nv_bfloat16& h, __nv_bfloat16& l) {
    h = __float2bfloat16(v);
    l = __float2bfloat16(v - __bfloat162float(h));
}
__device__ __forceinline__ void split2(float v0, float v1, uint32_t& hi, uint32_t& lo) {
    __nv_bfloat16 h0, l0, h1, l1;
    split1(v0, h0, l0); split1(v1, h1, l1);
    __nv_bfloat162 hp = __halves2bfloat162(h0, h1);
    __nv_bfloat162 lp = __halves2bfloat162(l0, l1);
    hi = *reinterpret_cast<uint32_t*>(&hp);
    lo = *reinterpret_cast<uint32_t*>(&lp);
}

// ---------------------------------------------------------------------------
// init: U/colsum/MT zero + pad rows [NN, PADK) of adj and h arrays
// ---------------------------------------------------------------------------
#define PADR (PADK - NN)   // 704
__global__ void init_kernel() {
    int i = blockIdx.x * blockDim.x + threadIdx.x;
    if (i < 384 * NF) g_U[i] = 0.f;
    if (i < 384) g_colsum[i] = 0.f;
    if (i < NF * NAP / 2) {
        reinterpret_cast<uint32_t*>(g_MT_hi)[i] = 0u;
        reinterpret_cast<uint32_t*>(g_MT_lo)[i] = 0u;
    }
    if (i < PADR * NAP / 2) {
        reinterpret_cast<uint32_t*>(g_adj_hi + (size_t)NN * NAP)[i] = 0u;
        reinterpret_cast<uint32_t*>(g_adj_lo + (size_t)NN * NAP)[i] = 0u;
    }
    if (i < PADR * NF / 2) {
        reinterpret_cast<uint32_t*>(g_hh + (size_t)NN * NF)[i] = 0u;
        reinterpret_cast<uint32_t*>(g_hl + (size_t)NN * NF)[i] = 0u;
    }
}

// ---------------------------------------------------------------------------
// adj -> bf16 hi/lo (padded 320 cols) + rowsum + colsum in one pass
// ---------------------------------------------------------------------------
__device__ __forceinline__ void w4(__nv_bfloat16* ph, __nv_bfloat16* pl, float4 v) {
    uint32_t hA, lA, hB, lB;
    split2(v.x, v.y, hA, lA);
    split2(v.z, v.w, hB, lB);
    *reinterpret_cast<uint2*>(ph) = make_uint2(hA, hB);
    *reinterpret_cast<uint2*>(pl) = make_uint2(lA, lB);
}

#define CONV_ROWS 250
__global__ void __launch_bounds__(256) conv_adj_kernel(const float* __restrict__ adj) {
    const int tx = threadIdx.x & 31;
    const int ty = threadIdx.x >> 5;
    const int r0 = blockIdx.x * CONV_ROWS;
    const int r1 = min(r0 + CONV_ROWS, NN);

    float ca[12];
#pragma unroll
    for (int j = 0; j < 12; j++) ca[j] = 0.f;

    for (int r = r0 + ty; r < r1; r += 8) {
        const float4* row4 = (const float4*)(adj + (size_t)r * NA);
        float4 v0 = row4[tx];
        float4 v1 = row4[32 + tx];
        float4 v2 = (tx < 11) ? row4[64 + tx] : make_float4(0.f, 0.f, 0.f, 0.f);
        ca[0] += v0.x; ca[1] += v0.y; ca[2]  += v0.z; ca[3]  += v0.w;
        ca[4] += v1.x; ca[5] += v1.y; ca[6]  += v1.z; ca[7]  += v1.w;
        ca[8] += v2.x; ca[9] += v2.y; ca[10] += v2.z; ca[11] += v2.w;
        float rp = v0.x + v0.y + v0.z + v0.w
                 + v1.x + v1.y + v1.z + v1.w
                 + v2.x + v2.y + v2.z + v2.w;
#pragma unroll
        for (int o = 16; o > 0; o >>= 1)
            rp += __shfl_down_sync(0xffffffffu, rp, o);
        if (tx == 0) g_rowsum[r] = rp;

        __nv_bfloat16* oh = g_adj_hi + (size_t)r * NAP;
        __nv_bfloat16* ol = g_adj_lo + (size_t)r * NAP;
        w4(oh + 4 * tx,        ol + 4 * tx,        v0);
        w4(oh + 4 * (32 + tx), ol + 4 * (32 + tx), v1);
        if (tx < 16) w4(oh + 4 * (64 + tx), ol + 4 * (64 + tx), v2);
    }

    __shared__ float sc[8][12][32];
#pragma unroll
    for (int j = 0; j < 12; j++) sc[ty][j][tx] = ca[j];
    __syncthreads();
    if (ty == 0) {
#pragma unroll
        for (int j = 0; j < 12; j++) {
            float s = 0.f;
#pragma unroll
            for (int t = 0; t < 8; t++) s += sc[t][j][tx];
            int col = (j >> 2) * 128 + tx * 4 + (j & 3);
            if (col < NA) atomicAdd(&g_colsum[col], s);
        }
    }
}

// ---------------------------------------------------------------------------
__global__ void conv_x_kernel(const float* __restrict__ x) {
    size_t i = (size_t)blockIdx.x * blockDim.x + threadIdx.x;
    if (i < (size_t)NN * NF / 4) {
        float4 v = ((const float4*)x)[i];
        uint32_t hA, lA, hB, lB;
        split2(v.x, v.y, hA, lA);
        split2(v.z, v.w, hB, lB);
        *reinterpret_cast<uint2*>(g_hh + 4 * i) = make_uint2(hA, hB);
        *reinterpret_cast<uint2*>(g_hl + 4 * i) = make_uint2(lA, lB);
    }
}

// ---------------------------------------------------------------------------
// upass: U[a][d] += sum_k adj[k][a]*h[k][d].
// grid(3, 98): anchor chunks {128, 128, 64}; each CTA covers the full feature
// dim so h tiles are read 3x total (was 5x). 256 thr, 8 warps.
// AW=128: warps 4a x 2d, warp tile 32a x 64d.  AW=64: 2a x 4d, 32a x 32d.
// ---------------------------------------------------------------------------
template<int AW>
__device__ __forceinline__ void upass_body(uint32_t sb, int a0, size_t k0, int tid) {
    constexpr int PA  = AW * 2 + 16;      // 272 or 144 (odd*16 -> conflict-free)
    constexpr int PB  = 272;
    constexpr int SAB = KT * PA;          // A buf bytes
    constexpr int SBB = KT * PB;          // B buf bytes
    constexpr int STG = 2 * SAB + 2 * SBB;
    constexpr int WN  = (AW == 128) ? 2 : 4;
    constexpr int ND  = 128 / WN;         // 64 or 32
    constexpr int N8  = ND / 8;           // 8 or 4
    constexpr int NBP = ND / 16;          // 4 or 2
    constexpr int ACH = KT * (AW / 8);    // A chunks per buf: 512 or 256

    const int wid = tid >> 5, L = tid & 31;
    const int warp_m = wid / WN, warp_n = wid % WN;

    float acc[2][N8][4];
#pragma unroll
    for (int i = 0; i < 2; i++)
#pragma unroll
        for (int j = 0; j < N8; j++)
#pragma unroll
            for (int q = 0; q < 4; q++) acc[i][j][q] = 0.f;

    auto load = [&](uint32_t base, size_t kt) {
#pragma unroll
        for (int it = 0; it < 2 * ACH / 256; it++) {
            int idx = tid + it * 256;
            int buf = idx / ACH, rem = idx % ACH;
            int row = rem / (AW / 8), c = rem % (AW / 8);
            const __nv_bfloat16* src = (buf ? g_adj_lo : g_adj_hi)
                                       + (kt + row) * NAP + a0 + c * 8;
            cpa(base + buf * SAB + row * PA + c * 16, src);
        }
#pragma unroll
        for (int it = 0; it < 4; it++) {     // B: 2 bufs x 512 chunks
            int idx = tid + it * 256;
            int buf = idx >> 9, rem = idx & 511;
            int row = rem >> 4, c = rem & 15;
            const __nv_bfloat16* src = (buf ? g_hl : g_hh) + (kt + row) * NF + c * 8;
            cpa(base + 2 * SAB + buf * SBB + row * PB + c * 16, src);
        }
    };

    load(sb, k0);
    cpa_commit();

    const int T = SLICE_K / KT;  // 64
    for (int t = 0; t < T; t++) {
        cpa_wait<0>();
        __syncthreads();
        if (t + 1 < T) {
            load(sb + ((t + 1) & 1) * STG, k0 + (size_t)(t + 1) * KT);
            cpa_commit();
        }
        const uint32_t st = sb + (t & 1) * STG;
        const uint32_t Ah = st, Al = st + SAB;
        const uint32_t Bh = st + 2 * SAB, Bl = Bh + SBB;

#pragma unroll
        for (int ks = 0; ks < 2; ks++) {
            const uint32_t aoff = (uint32_t)(ks * 16 + ((L >> 4) & 1) * 8 + (L & 7)) * PA
                                + ((L >> 3) & 1) * 16;
            uint32_t AF[2][2][4];
#pragma unroll
            for (int mb = 0; mb < 2; mb++) {
                uint32_t c2 = (uint32_t)(warp_m * 32 + mb * 16) * 2;
                ldm4t(AF[0][mb], Ah + aoff + c2);
                ldm4t(AF[1][mb], Al + aoff + c2);
            }
            const uint32_t boff = (uint32_t)(ks * 16 + ((L >> 3) & 1) * 8 + (L & 7)) * PB
                                + ((L >> 4) & 1) * 16;
#pragma unroll
            for (int nb = 0; nb < NBP; nb++) {
                uint32_t BH[4], BL[4];
                uint32_t c2 = (uint32_t)(warp_n * ND + nb * 16) * 2;
                ldm4t(BH, Bh + boff + c2);
                ldm4t(BL, Bl + boff + c2);
#pragma unroll
                for (int mb = 0; mb < 2; mb++)
#pragma unroll
                    for (int jj = 0; jj < 2; jj++) {
                        mma16816(acc[mb][nb * 2 + jj], AF[0][mb], &BH[jj * 2]);
                        mma16816(acc[mb][nb * 2 + jj], AF[0][mb], &BL[jj * 2]);
                        mma16816(acc[mb][nb * 2 + jj], AF[1][mb], &BH[jj * 2]);
                    }
            }
        }
    }

#pragma unroll
    for (int mb = 0; mb < 2; mb++) {
        int a = a0 + warp_m * 32 + mb * 16 + (L >> 2);
#pragma unroll
        for (int j = 0; j < N8; j++) {
            int d = warp_n * ND + j * 8 + (L & 3) * 2;
            if (a < NA) {
                atomicAdd(&g_U[a * NF + d],     acc[mb][j][0]);
                atomicAdd(&g_U[a * NF + d + 1], acc[mb][j][1]);
            }
            if (a + 8 < NA) {
                atomicAdd(&g_U[(a + 8) * NF + d],     acc[mb][j][2]);
                atomicAdd(&g_U[(a + 8) * NF + d + 1], acc[mb][j][3]);
            }
        }
    }
}

#define U_STAGE_MAX (2 * (KT * 272) + 2 * (KT * 272))   // AW=128 stage: 34816
__global__ void __launch_bounds__(256, 2) upass_kernel() {
    extern __shared__ char smem[];
    const uint32_t sb = smem_u32(smem);
    const size_t k0 = (size_t)blockIdx.y * SLICE_K;
    if (blockIdx.x < 2)
        upass_body<128>(sb, blockIdx.x * 128, k0, threadIdx.x);
    else
        upass_body<64>(sb, 256, k0, threadIdx.x);
}

// ---------------------------------------------------------------------------
// mkM: M^T[d][a] = (U[a] @ W)[d] / clamp(colsum[a]) as bf16 hi/lo; zero U row.
// ---------------------------------------------------------------------------
template<int DOUT>
__global__ void mkM_kernel(const float* __restrict__ W) {
    __shared__ float u_s[NF];
    const int a = blockIdx.x;
    const int d = threadIdx.x;
    u_s[d] = g_U[a * NF + d];
    __syncthreads();
    g_U[a * NF + d] = 0.f;
    if (d < DOUT) {
        float cinv = 1.f / fmaxf(g_colsum[a], 1e-12f);
        float acc = 0.f;
#pragma unroll 8
        for (int k = 0; k < NF; k++)
            acc += u_s[k] * W[k * DOUT + d];
        __nv_bfloat16 hb, lb;
        split1(acc * cinv, hb, lb);
        g_MT_hi[d * NAP + a] = hb;
        g_MT_lo[d * NAP + a] = lb;
    }
}

// ---------------------------------------------------------------------------
// ppass: C[n][d] = sum_a adj[n][a]*M[a][d]; epilogue scales by 1/rowsum,
// relu+re-split (hidden) or fp32 write (final). 512 thr, 16 warps.
// ---------------------------------------------------------------------------
template<int NOUT, bool FINAL>
__global__ void __launch_bounds__(512) ppass_kernel(float* __restrict__ out) {
    constexpr int WM = (NOUT == 128) ? 4 : 8;
    constexpr int WN = 16 / WM;
    constexpr int MT = 128 / WM;
    constexpr int NT = NOUT / WN;
    constexpr int MB = MT / 16;
    constexpr int N8 = NT / 8;
    constexpr int NBP = NT / 16;
    constexpr int P = 80;
    constexpr int SA = 128 * P;
    constexpr int SB = NOUT * P;
    constexpr int STG = 2 * SA + 2 * SB;
    constexpr int BCH = NOUT * 8;

    extern __shared__ char smem[];
    const uint32_t sb = smem_u32(smem);
    const int tid = threadIdx.x, wid = tid >> 5, L = tid & 31;
    const int warp_m = wid / WN, warp_n = wid % WN;
    const size_t n0 = (size_t)blockIdx.x * 128;

    float acc[MB][N8][4];
#pragma unroll
    for (int i = 0; i < MB; i++)
#pragma unroll
        for (int j = 0; j < N8; j++)
#pragma unroll
            for (int q = 0; q < 4; q++) acc[i][j][q] = 0.f;

    auto load_tile = [&](int t, int stage) {
        uint32_t base = sb + stage * STG;
#pragma unroll
        for (int it = 0; it < 2; it++) {           // A: bounds-free (padded rows)
            int idx = tid + it * 512;
            int buf = idx >> 9, rem = idx & 511;
            int row = rem >> 2, c = rem & 3;
            const __nv_bfloat16* src = (buf ? g_adj_lo : g_adj_hi)
                                       + (n0 + row) * NAP + t * KT + c * 8;
            cpa(base + buf * SA + row * P + c * 16, src);
        }
        if (tid < BCH) {
            int buf = tid / (BCH / 2), rem = tid % (BCH / 2);
            int row = rem >> 2, c = rem & 3;
            const __nv_bfloat16* src = (buf ? g_MT_lo : g_MT_hi) + row * NAP + t * KT + c * 8;
            cpa(base + 2 * SA + buf * SB + row * P + c * 16, src);
        }
        if (BCH > 512 && tid + 512 < BCH) {
            int idx = tid + 512;
            int buf = idx / (BCH / 2), rem = idx % (BCH / 2);
            int row = rem >> 2, c = rem & 3;
            const __nv_bfloat16* src = (buf ? g_MT_lo : g_MT_hi) + row * NAP + t * KT + c * 8;
            cpa(base + 2 * SA + buf * SB + row * P + c * 16, src);
        }
    };

    load_tile(0, 0);
    cpa_commit();

    const int T = NAP / KT;  // 10
    for (int t = 0; t < T; t++) {
        cpa_wait<0>();
        __syncthreads();
        if (t + 1 < T) {
            load_tile(t + 1, (t + 1) & 1);
            cpa_commit();
        }
        const uint32_t st = sb + (t & 1) * STG;
        const uint32_t Ah = st, Al = st + SA;
        const uint32_t Bh = st + 2 * SA, Bl = Bh + SB;

#pragma unroll
        for (int ks = 0; ks < 2; ks++) {
            const uint32_t aoff = (uint32_t)(((L >> 3) & 1) * 8 + (L & 7)) * P
                                + ks * 32 + ((L >> 4) & 1) * 16;
            uint32_t AF[2][MB][4];
#pragma unroll
            for (int mb = 0; mb < MB; mb++) {
                uint32_t ro = (uint32_t)(warp_m * MT + mb * 16) * P;
                ldm4(AF[0][mb], Ah + ro + aoff);
                ldm4(AF[1][mb], Al + ro + aoff);
            }
            const uint32_t boff = (uint32_t)(((L >> 4) & 1) * 8 + (L & 7)) * P
                                + ks * 32 + ((L >> 3) & 1) * 16;
            uint32_t BF[2][NBP][4];
#pragma unroll
            for (int nb = 0; nb < NBP; nb++) {
                uint32_t ro = (uint32_t)(warp_n * NT + nb * 16) * P;
                ldm4(BF[0][nb], Bh + ro + boff);
                ldm4(BF[1][nb], Bl + ro + boff);
            }
#pragma unroll
            for (int mb = 0; mb < MB; mb++)
#pragma unroll
                for (int j = 0; j < N8; j++) {
                    const uint32_t* bh = &BF[0][j >> 1][(j & 1) * 2];
                    const uint32_t* bl = &BF[1][j >> 1][(j & 1) * 2];
                    mma16816(acc[mb][j], AF[0][mb], bh);
                    mma16816(acc[mb][j], AF[0][mb], bl);
                    mma16816(acc[mb][j], AF[1][mb], bh);
                }
        }
    }

    // epilogue
#pragma unroll
    for (int mb = 0; mb < MB; mb++) {
        size_t r0 = n0 + warp_m * MT + mb * 16 + (L >> 2);
        size_t r1 = r0 + 8;
        float ri0 = (r0 < NN) ? 1.f / fmaxf(g_rowsum[r0], 1e-12f) : 0.f;
        float ri1 = (r1 < NN) ? 1.f / fmaxf(g_rowsum[r1], 1e-12f) : 0.f;
#pragma unroll
        for (int j = 0; j < N8; j++) {
            int d = warp_n * NT + j * 8 + (L & 3) * 2;
            if (FINAL) {
                if (r0 < NN) {
                    float2 o = make_float2(acc[mb][j][0] * ri0, acc[mb][j][1] * ri0);
                    *(float2*)(out + r0 * NC + d) = o;
                }
                if (r1 < NN) {
                    float2 o = make_float2(acc[mb][j][2] * ri1, acc[mb][j][3] * ri1);
                    *(float2*)(out + r1 * NC + d) = o;
                }
            } else {
                if (r0 < NN) {
                    float v0 = fmaxf(acc[mb][j][0] * ri0, 0.f);
                    float v1 = fmaxf(acc[mb][j][1] * ri0, 0.f);
                    uint32_t hi, lo;
                    split2(v0, v1, hi, lo);
                    *(uint32_t*)(g_hh + r0 * NF + d) = hi;
                    *(uint32_t*)(g_hl + r0 * NF + d) = lo;
                }
                if (r1 < NN) {
                    float v0 = fmaxf(acc[mb][j][2] * ri1, 0.f);
                    float v1 = fmaxf(acc[mb][j][3] * ri1, 0.f);
                    uint32_t hi, lo;
                    split2(v0, v1, hi, lo);
                    *(uint32_t*)(g_hh + r1 * NF + d) = hi;
                    *(uint32_t*)(g_hl + r1 * NF + d) = lo;
                }
            }
        }
    }
}

// ---------------------------------------------------------------------------
extern "C" void kernel_launch(void* const* d_in, const int* in_sizes, int n_in,
                              void* d_out, int out_size) {
    const float* x   = (const float*)d_in[0];
    const float* adj = (const float*)d_in[1];
    const float* W1  = (const float*)d_in[2];
    const float* W2  = (const float*)d_in[3];
    const float* W3  = (const float*)d_in[4];
    float* out = (float*)d_out;

    cudaFuncSetAttribute(upass_kernel,
                         cudaFuncAttributeMaxDynamicSharedMemorySize, 2 * U_STAGE_MAX);
    cudaFuncSetAttribute(ppass_kernel<128, false>,
                         cudaFuncAttributeMaxDynamicSharedMemorySize, 81920);
    cudaFuncSetAttribute(ppass_kernel<32, true>,
                         cudaFuncAttributeMaxDynamicSharedMemorySize, 51200);

    init_kernel<<<440, 256>>>();          // includes pad-row zeroing
    conv_adj_kernel<<<800, 256>>>(adj);
    conv_x_kernel<<<25600, 256>>>(x);

    dim3 ugrid(3, NSLICE);

    upass_kernel<<<ugrid, 256, 2 * U_STAGE_MAX>>>();
    mkM_kernel<128><<<NA, 128>>>(W1);
    ppass_kernel<128, false><<<1563, 512, 81920>>>(nullptr);

    upass_kernel<<<ugrid, 256, 2 * U_STAGE_MAX>>>();
    mkM_kernel<128><<<NA, 128>>>(W2);
    ppass_kernel<128, false><<<1563, 512, 81920>>>(nullptr);

    upass_kernel<<<ugrid, 256, 2 * U_STAGE_MAX>>>();
    mkM_kernel<32><<<NA, 128>>>(W3);
    ppass_kernel<32, true><<<1563, 512, 51200>>>(out);
}